// round 14
// baseline (speedup 1.0000x reference)
#include <cuda_runtime.h>
#include <cuda_fp16.h>
#include <cstdint>

#define N_NODES 50000
#define E_EDGES 800000
#define DIM     128
#define SCAN_NB 196   // ceil(N_NODES/256)
#define AS      136   // smem tile stride in halves (128 + 8 pad)
#define MT      64    // GEMM M-tile rows
#define XQ      (N_NODES * DIM / 4)   // float4 count of x
#define WQ      (DIM * DIM / 4)       // float4 count of one W

// ---------------- scratch (static device allocations; no cudaMalloc) -------
__device__ __half g_hh[N_NODES * DIM];     // features between layers (fp16)
__device__ __half g_hWh[N_NODES * DIM];    // dinv-scaled GEMM output (fp16)
__device__ __half g_Wh[3 * DIM * DIM];     // fp16 weights
__device__ float  g_dinv[N_NODES];         // 1/sqrt(deg)
__device__ int    g_deg[N_NODES];          // in-edge count (no self loop)
__device__ int    g_rowstart[N_NODES + 1]; // CSR offsets (in-edges)
__device__ int    g_off[N_NODES];          // fill cursors
__device__ int    g_csr_src[E_EDGES];      // src only (norm folded out)
__device__ int    g_bsum[SCAN_NB];
__device__ int    g_boff[SCAN_NB];

// ---------------- merged fp32 -> fp16 convert (x + 3 weights) --------------
__device__ __forceinline__ void cvt4(const float* __restrict__ in, __half* __restrict__ out, int q) {
    float4 v = ((const float4*)in)[q];
    __half2 h0 = __floats2half2_rn(v.x, v.y);
    __half2 h1 = __floats2half2_rn(v.z, v.w);
    uint2 p;
    p.x = *(unsigned*)&h0;
    p.y = *(unsigned*)&h1;
    ((uint2*)out)[q] = p;
}

__global__ void convert_all_kernel(const float* __restrict__ x,
                                   const float* __restrict__ W0,
                                   const float* __restrict__ W1,
                                   const float* __restrict__ W2) {
    int i = blockIdx.x * blockDim.x + threadIdx.x;
    if (i < XQ) { cvt4(x, g_hh, i); return; }
    int q = i - XQ;
    if (q < WQ)            { cvt4(W0, g_Wh,               q);          return; }
    if (q < 2 * WQ)        { cvt4(W1, g_Wh + DIM * DIM,   q - WQ);     return; }
    if (q < 3 * WQ)        { cvt4(W2, g_Wh + 2 * DIM * DIM, q - 2 * WQ); }
}

// ---------------- precompute kernels ---------------------------------------
__global__ void count_deg_kernel(const int* __restrict__ dst) {
    int i = blockIdx.x * blockDim.x + threadIdx.x;
    if (i >= E_EDGES / 4) return;
    int4 d = ((const int4*)dst)[i];
    atomicAdd(&g_deg[d.x], 1);
    atomicAdd(&g_deg[d.y], 1);
    atomicAdd(&g_deg[d.z], 1);
    atomicAdd(&g_deg[d.w], 1);
}

__device__ __forceinline__ int block_exclusive_scan_256(int v, int tid) {
    __shared__ int wsum[8];
    const int lane = tid & 31, wid = tid >> 5;
    int inc = v;
#pragma unroll
    for (int d = 1; d < 32; d <<= 1) {
        int y = __shfl_up_sync(0xffffffffu, inc, d);
        if (lane >= d) inc += y;
    }
    if (lane == 31) wsum[wid] = inc;
    __syncthreads();
    if (tid == 0) {
        int run = 0;
#pragma unroll
        for (int w = 0; w < 8; w++) { int t = wsum[w]; wsum[w] = run; run += t; }
    }
    __syncthreads();
    return wsum[wid] + inc - v;
}

__global__ __launch_bounds__(256) void scan_bsum_kernel() {
    __shared__ int wsum[8];
    const int tid = threadIdx.x;
    const int i = blockIdx.x * 256 + tid;
    int v = 0;
    if (i < N_NODES) {
        v = g_deg[i];
        g_dinv[i] = rsqrtf((float)(v + 1));   // +1 self loop
    }
    const int lane = tid & 31, wid = tid >> 5;
#pragma unroll
    for (int d = 16; d > 0; d >>= 1) v += __shfl_down_sync(0xffffffffu, v, d);
    if (lane == 0) wsum[wid] = v;
    __syncthreads();
    if (tid == 0) {
        int s = 0;
#pragma unroll
        for (int w = 0; w < 8; w++) s += wsum[w];
        g_bsum[blockIdx.x] = s;
    }
}

__global__ __launch_bounds__(256) void scan_boff_kernel() {
    const int tid = threadIdx.x;
    int v = (tid < SCAN_NB) ? g_bsum[tid] : 0;
    int e = block_exclusive_scan_256(v, tid);
    if (tid < SCAN_NB) g_boff[tid] = e;
    if (tid == SCAN_NB - 1) g_rowstart[N_NODES] = e + v;
}

__global__ __launch_bounds__(256) void scan_write_kernel() {
    const int tid = threadIdx.x;
    const int i = blockIdx.x * 256 + tid;
    int v = (i < N_NODES) ? g_deg[i] : 0;
    int e = block_exclusive_scan_256(v, tid) + g_boff[blockIdx.x];
    if (i < N_NODES) { g_rowstart[i] = e; g_off[i] = e; }
}

__global__ void fill_csr_kernel(const int* __restrict__ src, const int* __restrict__ dst) {
    int i = blockIdx.x * blockDim.x + threadIdx.x;
    if (i >= E_EDGES / 4) return;
    int4 s = ((const int4*)src)[i];
    int4 d = ((const int4*)dst)[i];
    g_csr_src[atomicAdd(&g_off[d.x], 1)] = s.x;
    g_csr_src[atomicAdd(&g_off[d.y], 1)] = s.y;
    g_csr_src[atomicAdd(&g_off[d.z], 1)] = s.z;
    g_csr_src[atomicAdd(&g_off[d.w], 1)] = s.w;
}

// ---------------- HGEMM via mma.sync (tensor cores) ------------------------
__device__ __forceinline__ void ldsm_x4(unsigned r[4], unsigned addr) {
    asm volatile("ldmatrix.sync.aligned.m8n8.x4.shared.b16 {%0,%1,%2,%3}, [%4];"
                 : "=r"(r[0]), "=r"(r[1]), "=r"(r[2]), "=r"(r[3]) : "r"(addr));
}
__device__ __forceinline__ void ldsm_x4_trans(unsigned r[4], unsigned addr) {
    asm volatile("ldmatrix.sync.aligned.m8n8.x4.trans.shared.b16 {%0,%1,%2,%3}, [%4];"
                 : "=r"(r[0]), "=r"(r[1]), "=r"(r[2]), "=r"(r[3]) : "r"(addr));
}
__device__ __forceinline__ void mma_16816(float c[4], const unsigned a[4], const unsigned b[2]) {
    asm volatile("mma.sync.aligned.m16n8k16.row.col.f32.f16.f16.f32 "
                 "{%0,%1,%2,%3}, {%4,%5,%6,%7}, {%8,%9}, {%0,%1,%2,%3};"
                 : "+f"(c[0]), "+f"(c[1]), "+f"(c[2]), "+f"(c[3])
                 : "r"(a[0]), "r"(a[1]), "r"(a[2]), "r"(a[3]), "r"(b[0]), "r"(b[1]));
}

// C[M,128](fp16) = dinv[row] * (A[M,128](fp16) @ W[128,128](fp16)), fp32 acc.
// 64x128 block tile, 8 warps: 4 along M (16 rows), 2 along N (64 cols).
__global__ __launch_bounds__(256)
void hgemm128_kernel(const __half* __restrict__ A, const __half* __restrict__ W,
                     __half* __restrict__ C, int M) {
    extern __shared__ __align__(16) __half sm[];
    __half* Asm = sm;                  // [MT][AS]
    __half* Bsm = sm + MT * AS;        // [128][AS]

    const int tid   = threadIdx.x;
    const int brow0 = blockIdx.x * MT;

    // stage A (64 rows) + W (128 rows): (64+128)*16 = 3072 uint4 over 256 thr
#pragma unroll
    for (int i = 0; i < 4; i++) {      // A: 1024 uint4
        int idx = tid + i * 256;
        int r   = idx >> 4;
        int c8  = idx & 15;
        int gr  = brow0 + r;
        uint4 v = make_uint4(0u, 0u, 0u, 0u);
        if (gr < M) v = ((const uint4*)(A + (size_t)gr * DIM))[c8];
        *(uint4*)&Asm[r * AS + c8 * 8] = v;
    }
#pragma unroll
    for (int i = 0; i < 8; i++) {      // W: 2048 uint4
        int idx = tid + i * 256;
        int r   = idx >> 4;
        int c8  = idx & 15;
        uint4 w = ((const uint4*)(W + (size_t)r * DIM))[c8];
        *(uint4*)&Bsm[r * AS + c8 * 8] = w;
    }
    __syncthreads();

    const int warp = tid >> 5, lane = tid & 31;
    const int m0 = (warp & 3) * 16;    // warp M origin (16 rows)
    const int n0 = (warp >> 2) * 64;   // warp N origin (64 cols)
    const int l15 = lane & 15;
    const int lhi = lane >> 4;

    float c[8][4];
#pragma unroll
    for (int n = 0; n < 8; n++)
#pragma unroll
        for (int q = 0; q < 4; q++) c[n][q] = 0.0f;

#pragma unroll
    for (int kk = 0; kk < 8; kk++) {
        const int k0 = kk * 16;
        unsigned a[4];
        {
            unsigned ad = (unsigned)__cvta_generic_to_shared(
                &Asm[(m0 + l15) * AS + k0 + lhi * 8]);
            ldsm_x4(a, ad);
        }
        unsigned b[8][2];
#pragma unroll
        for (int j = 0; j < 4; j++) {
            unsigned ad = (unsigned)__cvta_generic_to_shared(
                &Bsm[(k0 + l15) * AS + n0 + j * 16 + lhi * 8]);
            unsigned r[4];
            ldsm_x4_trans(r, ad);
            b[2 * j][0]     = r[0]; b[2 * j][1]     = r[1];
            b[2 * j + 1][0] = r[2]; b[2 * j + 1][1] = r[3];
        }
#pragma unroll
        for (int n = 0; n < 8; n++)
            mma_16816(c[n], a, b[n]);
    }

    // epilogue: scale rows by dinv, convert to fp16
    const int rq = lane >> 2;
    const int cq = (lane & 3) * 2;
    {
        int row0 = brow0 + m0 + rq;
        int row1 = row0 + 8;
        float d0 = (row0 < M) ? g_dinv[row0] : 0.f;
        float d1 = (row1 < M) ? g_dinv[row1] : 0.f;
#pragma unroll
        for (int n = 0; n < 8; n++) {
            int col = n0 + n * 8 + cq;
            if (row0 < M) {
                __half2 h = __floats2half2_rn(d0 * c[n][0], d0 * c[n][1]);
                *(__half2*)&C[(size_t)row0 * DIM + col] = h;
            }
            if (row1 < M) {
                __half2 h = __floats2half2_rn(d1 * c[n][2], d1 * c[n][3]);
                *(__half2*)&C[(size_t)row1 * DIM + col] = h;
            }
        }
    }
}

// ---------------- aggregate: warp per node, unweighted pull over CSR -------
#define AGG_BODY()                                                           \
    const int gw   = (blockIdx.x * blockDim.x + threadIdx.x) >> 5;           \
    const int lane = threadIdx.x & 31;                                       \
    if (gw >= N_NODES) return;                                               \
    float4 acc;                                                              \
    {                                                                        \
        uint2 pv = hw2[(size_t)gw * 32 + lane];                              \
        __half2 p0 = *(__half2*)&pv.x, p1 = *(__half2*)&pv.y;                \
        float2 f0 = __half22float2(p0), f1 = __half22float2(p1);             \
        acc.x = f0.x; acc.y = f0.y; acc.z = f1.x; acc.w = f1.y;              \
    }                                                                        \
    int j  = g_rowstart[gw];                                                 \
    const int je = g_rowstart[gw + 1];                                       \
    for (; j + 4 <= je; j += 4) {                                            \
        AGG_ONE(j); AGG_ONE(j + 1); AGG_ONE(j + 2); AGG_ONE(j + 3);          \
    }                                                                        \
    for (; j < je; j++) AGG_ONE(j);                                          \
    const float dn = g_dinv[gw];                                             \
    float4 res = ((const float4*)bias)[lane];                                \
    res.x = fmaf(dn, acc.x, res.x);                                          \
    res.y = fmaf(dn, acc.y, res.y);                                          \
    res.z = fmaf(dn, acc.z, res.z);                                          \
    res.w = fmaf(dn, acc.w, res.w);

#define AGG_ONE(idx)                                                     \
    {                                                                    \
        int _s = g_csr_src[(idx)];                                       \
        uint2 _pv = hw2[(size_t)_s * 32 + lane];                         \
        __half2 _p0 = *(__half2*)&_pv.x, _p1 = *(__half2*)&_pv.y;        \
        float2 _f0 = __half22float2(_p0), _f1 = __half22float2(_p1);     \
        acc.x += _f0.x; acc.y += _f0.y; acc.z += _f1.x; acc.w += _f1.y;  \
    }

// hidden layers: relu, fp16 output
__global__ __launch_bounds__(256)
void aggregate_h_kernel(const uint2* __restrict__ hw2, const float* __restrict__ bias,
                        __half* __restrict__ out) {
    AGG_BODY();
    res.x = fmaxf(res.x, 0.f);
    res.y = fmaxf(res.y, 0.f);
    res.z = fmaxf(res.z, 0.f);
    res.w = fmaxf(res.w, 0.f);
    __half2 o0 = __floats2half2_rn(res.x, res.y);
    __half2 o1 = __floats2half2_rn(res.z, res.w);
    uint2 p;
    p.x = *(unsigned*)&o0;
    p.y = *(unsigned*)&o1;
    *(uint2*)&out[(size_t)gw * DIM + lane * 4] = p;
}

// final layer: residual, fp32 output
__global__ __launch_bounds__(256)
void aggregate_f_kernel(const uint2* __restrict__ hw2, const float* __restrict__ bias,
                        const float* __restrict__ resid, float* __restrict__ out) {
    AGG_BODY();
    float4 r = ((const float4*)resid)[(size_t)gw * 32 + lane];
    res.x += r.x; res.y += r.y; res.z += r.z; res.w += r.w;
    ((float4*)out)[(size_t)gw * 32 + lane] = res;
}
#undef AGG_ONE
#undef AGG_BODY

// ---------------- launch ----------------------------------------------------
extern "C" void kernel_launch(void* const* d_in, const int* in_sizes, int n_in,
                              void* d_out, int out_size) {
    const float* x   = (const float*)d_in[0];
    const int*   ei  = (const int*)d_in[1];
    const int*   src = ei;
    const int*   dst = ei + E_EDGES;
    const float* W0  = (const float*)d_in[2];
    const float* b0  = (const float*)d_in[3];
    const float* W1  = (const float*)d_in[4];
    const float* b1  = (const float*)d_in[5];
    const float* W2  = (const float*)d_in[6];
    const float* b2  = (const float*)d_in[7];
    float* out = (float*)d_out;

    __half *hPtr = nullptr, *hWPtr = nullptr, *WhPtr = nullptr;
    int    *degPtr = nullptr;
    cudaGetSymbolAddress((void**)&hPtr,  g_hh);
    cudaGetSymbolAddress((void**)&hWPtr, g_hWh);
    cudaGetSymbolAddress((void**)&WhPtr, g_Wh);
    cudaGetSymbolAddress((void**)&degPtr, g_deg);
    const uint2* hw2 = (const uint2*)hWPtr;

    const int smem = (MT + 128) * AS * (int)sizeof(__half);   // 52224
    static int once = 0;
    static cudaStream_t s1;
    static cudaEvent_t evFork, evDinv, evJoin;
    if (!once) {
        cudaFuncSetAttribute(hgemm128_kernel,
                             cudaFuncAttributeMaxDynamicSharedMemorySize, smem);
        cudaStreamCreateWithFlags(&s1, cudaStreamNonBlocking);
        cudaEventCreateWithFlags(&evFork, cudaEventDisableTiming);
        cudaEventCreateWithFlags(&evDinv, cudaEventDisableTiming);
        cudaEventCreateWithFlags(&evJoin, cudaEventDisableTiming);
        once = 1;
    }

    const int e4blk = (E_EDGES / 4 + 255) / 256;             // 782
    const int gblk  = (N_NODES + MT - 1) / MT;               // 782
    const int ablk  = (N_NODES * 32 + 255) / 256;            // 6250
    const int cblk  = (XQ + 3 * WQ + 255) / 256;             // 6298

    // ---- fork -------------------------------------------------------------
    cudaEventRecord(evFork, 0);
    cudaStreamWaitEvent(s1, evFork, 0);

    // branch A (s1): converts; GEMM0 after dinv is ready
    convert_all_kernel<<<cblk, 256, 0, s1>>>(x, W0, W1, W2);

    // branch B (main): degree + dinv
    cudaMemsetAsync(degPtr, 0, N_NODES * sizeof(int), 0);
    count_deg_kernel<<<e4blk, 256>>>(dst);
    scan_bsum_kernel<<<SCAN_NB, 256>>>();     // also writes dinv
    cudaEventRecord(evDinv, 0);

    // branch A continues: GEMM0 (needs dinv for row scaling)
    cudaStreamWaitEvent(s1, evDinv, 0);
    hgemm128_kernel<<<gblk, 256, smem, s1>>>(hPtr, WhPtr, hWPtr, N_NODES);
    cudaEventRecord(evJoin, s1);

    // branch B continues: scan + CSR fill
    scan_boff_kernel<<<1, 256>>>();
    scan_write_kernel<<<SCAN_NB, 256>>>();
    fill_csr_kernel<<<e4blk, 256>>>(src, dst);

    // ---- join --------------------------------------------------------------
    cudaStreamWaitEvent(0, evJoin, 0);

    // layer 0 aggregate
    aggregate_h_kernel<<<ablk, 256>>>(hw2, b0, hPtr);

    // layer 1
    hgemm128_kernel<<<gblk, 256, smem>>>(hPtr, WhPtr + DIM * DIM, hWPtr, N_NODES);
    aggregate_h_kernel<<<ablk, 256>>>(hw2, b1, hPtr);

    // layer 2: out = agg(hW) + b2 + x
    hgemm128_kernel<<<gblk, 256, smem>>>(hPtr, WhPtr + 2 * DIM * DIM, hWPtr, N_NODES);
    aggregate_f_kernel<<<ablk, 256>>>(hw2, b2, x, out);
}

// round 15
// speedup vs baseline: 1.0783x; 1.0783x over previous
#include <cuda_runtime.h>
#include <cuda_fp16.h>
#include <cstdint>

#define N_NODES 50000
#define E_EDGES 800000
#define DIM     128
#define SCAN_NB 196   // ceil(N_NODES/256)
#define AS      136   // smem tile stride in halves (128 + 8 pad)
#define XQ      (N_NODES * DIM / 4)   // float4 count of x
#define WQ      (DIM * DIM / 4)       // float4 count of one W

// ---------------- scratch (static device allocations; no cudaMalloc) -------
__device__ __half g_hh[N_NODES * DIM];     // features between layers (fp16)
__device__ __half g_hWh[N_NODES * DIM];    // dinv-scaled GEMM output (fp16)
__device__ __half g_Wh[3 * DIM * DIM];     // fp16 weights
__device__ float  g_dinv[N_NODES];         // 1/sqrt(deg)
__device__ int    g_deg[N_NODES];          // in-edge count (no self loop)
__device__ int    g_rowstart[N_NODES + 1]; // CSR offsets (in-edges)
__device__ int    g_off[N_NODES];          // fill cursors
__device__ int    g_csr_src[E_EDGES];      // src only (norm folded out)
__device__ int    g_bsum[SCAN_NB];
__device__ int    g_boff[SCAN_NB];

// ---------------- merged fp32 -> fp16 convert (x + 3 weights) --------------
__device__ __forceinline__ void cvt4(const float* __restrict__ in, __half* __restrict__ out, int q) {
    float4 v = ((const float4*)in)[q];
    __half2 h0 = __floats2half2_rn(v.x, v.y);
    __half2 h1 = __floats2half2_rn(v.z, v.w);
    uint2 p;
    p.x = *(unsigned*)&h0;
    p.y = *(unsigned*)&h1;
    ((uint2*)out)[q] = p;
}

__global__ void convert_all_kernel(const float* __restrict__ x,
                                   const float* __restrict__ W0,
                                   const float* __restrict__ W1,
                                   const float* __restrict__ W2) {
    int i = blockIdx.x * blockDim.x + threadIdx.x;
    if (i < XQ) { cvt4(x, g_hh, i); return; }
    int q = i - XQ;
    if (q < WQ)            { cvt4(W0, g_Wh,               q);          return; }
    if (q < 2 * WQ)        { cvt4(W1, g_Wh + DIM * DIM,   q - WQ);     return; }
    if (q < 3 * WQ)        { cvt4(W2, g_Wh + 2 * DIM * DIM, q - 2 * WQ); }
}

// ---------------- precompute kernels ---------------------------------------
__global__ void count_deg_kernel(const int* __restrict__ dst) {
    int i = blockIdx.x * blockDim.x + threadIdx.x;
    if (i >= E_EDGES / 4) return;
    int4 d = ((const int4*)dst)[i];
    atomicAdd(&g_deg[d.x], 1);
    atomicAdd(&g_deg[d.y], 1);
    atomicAdd(&g_deg[d.z], 1);
    atomicAdd(&g_deg[d.w], 1);
}

__device__ __forceinline__ int block_exclusive_scan_256(int v, int tid) {
    __shared__ int wsum[8];
    const int lane = tid & 31, wid = tid >> 5;
    int inc = v;
#pragma unroll
    for (int d = 1; d < 32; d <<= 1) {
        int y = __shfl_up_sync(0xffffffffu, inc, d);
        if (lane >= d) inc += y;
    }
    if (lane == 31) wsum[wid] = inc;
    __syncthreads();
    if (tid == 0) {
        int run = 0;
#pragma unroll
        for (int w = 0; w < 8; w++) { int t = wsum[w]; wsum[w] = run; run += t; }
    }
    __syncthreads();
    return wsum[wid] + inc - v;
}

__global__ __launch_bounds__(256) void scan_bsum_kernel() {
    __shared__ int wsum[8];
    const int tid = threadIdx.x;
    const int i = blockIdx.x * 256 + tid;
    int v = 0;
    if (i < N_NODES) {
        v = g_deg[i];
        g_dinv[i] = rsqrtf((float)(v + 1));   // +1 self loop
    }
    const int lane = tid & 31, wid = tid >> 5;
#pragma unroll
    for (int d = 16; d > 0; d >>= 1) v += __shfl_down_sync(0xffffffffu, v, d);
    if (lane == 0) wsum[wid] = v;
    __syncthreads();
    if (tid == 0) {
        int s = 0;
#pragma unroll
        for (int w = 0; w < 8; w++) s += wsum[w];
        g_bsum[blockIdx.x] = s;
    }
}

__global__ __launch_bounds__(256) void scan_boff_kernel() {
    const int tid = threadIdx.x;
    int v = (tid < SCAN_NB) ? g_bsum[tid] : 0;
    int e = block_exclusive_scan_256(v, tid);
    if (tid < SCAN_NB) g_boff[tid] = e;
    if (tid == SCAN_NB - 1) g_rowstart[N_NODES] = e + v;
}

__global__ __launch_bounds__(256) void scan_write_kernel() {
    const int tid = threadIdx.x;
    const int i = blockIdx.x * 256 + tid;
    int v = (i < N_NODES) ? g_deg[i] : 0;
    int e = block_exclusive_scan_256(v, tid) + g_boff[blockIdx.x];
    if (i < N_NODES) { g_rowstart[i] = e; g_off[i] = e; }
}

__global__ void fill_csr_kernel(const int* __restrict__ src, const int* __restrict__ dst) {
    int i = blockIdx.x * blockDim.x + threadIdx.x;
    if (i >= E_EDGES / 4) return;
    int4 s = ((const int4*)src)[i];
    int4 d = ((const int4*)dst)[i];
    g_csr_src[atomicAdd(&g_off[d.x], 1)] = s.x;
    g_csr_src[atomicAdd(&g_off[d.y], 1)] = s.y;
    g_csr_src[atomicAdd(&g_off[d.z], 1)] = s.z;
    g_csr_src[atomicAdd(&g_off[d.w], 1)] = s.w;
}

// ---------------- HGEMM via mma.sync (tensor cores) ------------------------
__device__ __forceinline__ void ldsm_x4(unsigned r[4], unsigned addr) {
    asm volatile("ldmatrix.sync.aligned.m8n8.x4.shared.b16 {%0,%1,%2,%3}, [%4];"
                 : "=r"(r[0]), "=r"(r[1]), "=r"(r[2]), "=r"(r[3]) : "r"(addr));
}
__device__ __forceinline__ void ldsm_x4_trans(unsigned r[4], unsigned addr) {
    asm volatile("ldmatrix.sync.aligned.m8n8.x4.trans.shared.b16 {%0,%1,%2,%3}, [%4];"
                 : "=r"(r[0]), "=r"(r[1]), "=r"(r[2]), "=r"(r[3]) : "r"(addr));
}
__device__ __forceinline__ void mma_16816(float c[4], const unsigned a[4], const unsigned b[2]) {
    asm volatile("mma.sync.aligned.m16n8k16.row.col.f32.f16.f16.f32 "
                 "{%0,%1,%2,%3}, {%4,%5,%6,%7}, {%8,%9}, {%0,%1,%2,%3};"
                 : "+f"(c[0]), "+f"(c[1]), "+f"(c[2]), "+f"(c[3])
                 : "r"(a[0]), "r"(a[1]), "r"(a[2]), "r"(a[3]), "r"(b[0]), "r"(b[1]));
}

// C[M,128](fp16) = dinv[row] * (A[M,128](fp16) @ W[128,128](fp16)), fp32 acc.
// 128x128 block tile, 512 threads, 16 warps in 4x4 grid: warp tile 32x32.
__global__ __launch_bounds__(512)
void hgemm128_kernel(const __half* __restrict__ A, const __half* __restrict__ W,
                     __half* __restrict__ C, int M) {
    extern __shared__ __align__(16) __half sm[];
    __half* Asm = sm;                  // [128][AS]
    __half* Bsm = sm + 128 * AS;       // [128][AS]

    const int tid   = threadIdx.x;
    const int brow0 = blockIdx.x * 128;

    // stage A (128 rows) + W (128 rows): 2048 + 2048 uint4 over 512 threads
#pragma unroll
    for (int i = 0; i < 4; i++) {
        int idx = tid + i * 512;       // 0..2047
        int r   = idx >> 4;
        int c8  = idx & 15;
        int gr  = brow0 + r;
        uint4 v = make_uint4(0u, 0u, 0u, 0u);
        if (gr < M) v = ((const uint4*)(A + (size_t)gr * DIM))[c8];
        *(uint4*)&Asm[r * AS + c8 * 8] = v;
        uint4 w = ((const uint4*)(W + (size_t)r * DIM))[c8];
        *(uint4*)&Bsm[r * AS + c8 * 8] = w;
    }
    __syncthreads();

    const int warp = tid >> 5, lane = tid & 31;
    const int m0 = (warp & 3) * 32;    // warp M origin (32 rows)
    const int n0 = (warp >> 2) * 32;   // warp N origin (32 cols)
    const int l15 = lane & 15;
    const int lhi = lane >> 4;

    float c[2][4][4];
#pragma unroll
    for (int t = 0; t < 2; t++)
#pragma unroll
        for (int n = 0; n < 4; n++)
#pragma unroll
            for (int q = 0; q < 4; q++) c[t][n][q] = 0.0f;

#pragma unroll
    for (int kk = 0; kk < 8; kk++) {
        const int k0 = kk * 16;
        unsigned a[2][4];
#pragma unroll
        for (int t = 0; t < 2; t++) {
            unsigned ad = (unsigned)__cvta_generic_to_shared(
                &Asm[(m0 + t * 16 + l15) * AS + k0 + lhi * 8]);
            ldsm_x4(a[t], ad);
        }
        unsigned b[4][2];
#pragma unroll
        for (int j = 0; j < 2; j++) {
            unsigned ad = (unsigned)__cvta_generic_to_shared(
                &Bsm[(k0 + l15) * AS + n0 + j * 16 + lhi * 8]);
            unsigned r[4];
            ldsm_x4_trans(r, ad);
            b[2 * j][0]     = r[0]; b[2 * j][1]     = r[1];
            b[2 * j + 1][0] = r[2]; b[2 * j + 1][1] = r[3];
        }
#pragma unroll
        for (int t = 0; t < 2; t++)
#pragma unroll
            for (int n = 0; n < 4; n++)
                mma_16816(c[t][n], a[t], b[n]);
    }

    // epilogue: scale rows by dinv, convert to fp16
    const int rq = lane >> 2;
    const int cq = (lane & 3) * 2;
#pragma unroll
    for (int t = 0; t < 2; t++) {
        int row0 = brow0 + m0 + t * 16 + rq;
        int row1 = row0 + 8;
        float d0 = (row0 < M) ? g_dinv[row0] : 0.f;
        float d1 = (row1 < M) ? g_dinv[row1] : 0.f;
#pragma unroll
        for (int n = 0; n < 4; n++) {
            int col = n0 + n * 8 + cq;
            if (row0 < M) {
                __half2 h = __floats2half2_rn(d0 * c[t][n][0], d0 * c[t][n][1]);
                *(__half2*)&C[(size_t)row0 * DIM + col] = h;
            }
            if (row1 < M) {
                __half2 h = __floats2half2_rn(d1 * c[t][n][2], d1 * c[t][n][3]);
                *(__half2*)&C[(size_t)row1 * DIM + col] = h;
            }
        }
    }
}

// ---------------- aggregate: warp per node, unweighted pull over CSR -------
#define AGG_BODY()                                                           \
    const int gw   = (blockIdx.x * blockDim.x + threadIdx.x) >> 5;           \
    const int lane = threadIdx.x & 31;                                       \
    if (gw >= N_NODES) return;                                               \
    float4 acc;                                                              \
    {                                                                        \
        uint2 pv = hw2[(size_t)gw * 32 + lane];                              \
        __half2 p0 = *(__half2*)&pv.x, p1 = *(__half2*)&pv.y;                \
        float2 f0 = __half22float2(p0), f1 = __half22float2(p1);             \
        acc.x = f0.x; acc.y = f0.y; acc.z = f1.x; acc.w = f1.y;              \
    }                                                                        \
    int j  = g_rowstart[gw];                                                 \
    const int je = g_rowstart[gw + 1];                                       \
    for (; j + 4 <= je; j += 4) {                                            \
        AGG_ONE(j); AGG_ONE(j + 1); AGG_ONE(j + 2); AGG_ONE(j + 3);          \
    }                                                                        \
    for (; j < je; j++) AGG_ONE(j);                                          \
    const float dn = g_dinv[gw];                                             \
    float4 res = ((const float4*)bias)[lane];                                \
    res.x = fmaf(dn, acc.x, res.x);                                          \
    res.y = fmaf(dn, acc.y, res.y);                                          \
    res.z = fmaf(dn, acc.z, res.z);                                          \
    res.w = fmaf(dn, acc.w, res.w);

#define AGG_ONE(idx)                                                     \
    {                                                                    \
        int _s = g_csr_src[(idx)];                                       \
        uint2 _pv = hw2[(size_t)_s * 32 + lane];                         \
        __half2 _p0 = *(__half2*)&_pv.x, _p1 = *(__half2*)&_pv.y;        \
        float2 _f0 = __half22float2(_p0), _f1 = __half22float2(_p1);     \
        acc.x += _f0.x; acc.y += _f0.y; acc.z += _f1.x; acc.w += _f1.y;  \
    }

// hidden layers: relu, fp16 output
__global__ __launch_bounds__(256)
void aggregate_h_kernel(const uint2* __restrict__ hw2, const float* __restrict__ bias,
                        __half* __restrict__ out) {
    AGG_BODY();
    res.x = fmaxf(res.x, 0.f);
    res.y = fmaxf(res.y, 0.f);
    res.z = fmaxf(res.z, 0.f);
    res.w = fmaxf(res.w, 0.f);
    __half2 o0 = __floats2half2_rn(res.x, res.y);
    __half2 o1 = __floats2half2_rn(res.z, res.w);
    uint2 p;
    p.x = *(unsigned*)&o0;
    p.y = *(unsigned*)&o1;
    *(uint2*)&out[(size_t)gw * DIM + lane * 4] = p;
}

// final layer: residual, fp32 output
__global__ __launch_bounds__(256)
void aggregate_f_kernel(const uint2* __restrict__ hw2, const float* __restrict__ bias,
                        const float* __restrict__ resid, float* __restrict__ out) {
    AGG_BODY();
    float4 r = ((const float4*)resid)[(size_t)gw * 32 + lane];
    res.x += r.x; res.y += r.y; res.z += r.z; res.w += r.w;
    ((float4*)out)[(size_t)gw * 32 + lane] = res;
}
#undef AGG_ONE
#undef AGG_BODY

// ---------------- launch ----------------------------------------------------
extern "C" void kernel_launch(void* const* d_in, const int* in_sizes, int n_in,
                              void* d_out, int out_size) {
    const float* x   = (const float*)d_in[0];
    const int*   ei  = (const int*)d_in[1];
    const int*   src = ei;
    const int*   dst = ei + E_EDGES;
    const float* W0  = (const float*)d_in[2];
    const float* b0  = (const float*)d_in[3];
    const float* W1  = (const float*)d_in[4];
    const float* b1  = (const float*)d_in[5];
    const float* W2  = (const float*)d_in[6];
    const float* b2  = (const float*)d_in[7];
    float* out = (float*)d_out;

    __half *hPtr = nullptr, *hWPtr = nullptr, *WhPtr = nullptr;
    int    *degPtr = nullptr;
    cudaGetSymbolAddress((void**)&hPtr,  g_hh);
    cudaGetSymbolAddress((void**)&hWPtr, g_hWh);
    cudaGetSymbolAddress((void**)&WhPtr, g_Wh);
    cudaGetSymbolAddress((void**)&degPtr, g_deg);
    const uint2* hw2 = (const uint2*)hWPtr;

    const int smem = 2 * 128 * AS * (int)sizeof(__half);   // 69632
    static int once = 0;
    static cudaStream_t s1;
    static cudaEvent_t evFork, evDinv, evJoin;
    if (!once) {
        cudaFuncSetAttribute(hgemm128_kernel,
                             cudaFuncAttributeMaxDynamicSharedMemorySize, smem);
        cudaStreamCreateWithFlags(&s1, cudaStreamNonBlocking);
        cudaEventCreateWithFlags(&evFork, cudaEventDisableTiming);
        cudaEventCreateWithFlags(&evDinv, cudaEventDisableTiming);
        cudaEventCreateWithFlags(&evJoin, cudaEventDisableTiming);
        once = 1;
    }

    const int e4blk = (E_EDGES / 4 + 255) / 256;             // 782
    const int gblk  = (N_NODES + 127) / 128;                 // 391
    const int ablk  = (N_NODES * 32 + 255) / 256;            // 6250
    const int cblk  = (XQ + 3 * WQ + 255) / 256;             // 6298

    // ---- fork -------------------------------------------------------------
    cudaEventRecord(evFork, 0);
    cudaStreamWaitEvent(s1, evFork, 0);

    // branch A (s1): converts; GEMM0 after dinv is ready
    convert_all_kernel<<<cblk, 256, 0, s1>>>(x, W0, W1, W2);

    // branch B (main): degree + dinv
    cudaMemsetAsync(degPtr, 0, N_NODES * sizeof(int), 0);
    count_deg_kernel<<<e4blk, 256>>>(dst);
    scan_bsum_kernel<<<SCAN_NB, 256>>>();     // also writes dinv
    cudaEventRecord(evDinv, 0);

    // branch A continues: GEMM0 (needs dinv for row scaling)
    cudaStreamWaitEvent(s1, evDinv, 0);
    hgemm128_kernel<<<gblk, 512, smem, s1>>>(hPtr, WhPtr, hWPtr, N_NODES);
    cudaEventRecord(evJoin, s1);

    // branch B continues: scan + CSR fill
    scan_boff_kernel<<<1, 256>>>();
    scan_write_kernel<<<SCAN_NB, 256>>>();
    fill_csr_kernel<<<e4blk, 256>>>(src, dst);

    // ---- join --------------------------------------------------------------
    cudaStreamWaitEvent(0, evJoin, 0);

    // layer 0 aggregate
    aggregate_h_kernel<<<ablk, 256>>>(hw2, b0, hPtr);

    // layer 1
    hgemm128_kernel<<<gblk, 512, smem>>>(hPtr, WhPtr + DIM * DIM, hWPtr, N_NODES);
    aggregate_h_kernel<<<ablk, 256>>>(hw2, b1, hPtr);

    // layer 2: out = agg(hW) + b2 + x
    hgemm128_kernel<<<gblk, 512, smem>>>(hPtr, WhPtr + 2 * DIM * DIM, hWPtr, N_NODES);
    aggregate_f_kernel<<<ablk, 256>>>(hw2, b2, x, out);
}